// round 3
// baseline (speedup 1.0000x reference)
#include <cuda_runtime.h>
#include <cuda_fp16.h>
#include <cstdint>
#include <cmath>

#define DX 1024
#define DK 128
#define SEQ 2048
#define MTOT (8*SEQ)

__device__ __half g_Khi[MTOT*DK];
__device__ __half g_Klo[MTOT*DK];
__device__ __half g_Vhi[MTOT*DK];
__device__ __half g_Vlo[MTOT*DK];

__device__ __forceinline__ uint32_t sptr(const void* p){
    return (uint32_t)__cvta_generic_to_shared(p);
}
__device__ __forceinline__ void ldm4(uint32_t* r, uint32_t a){
    asm volatile("ldmatrix.sync.aligned.m8n8.x4.shared.b16 {%0,%1,%2,%3}, [%4];"
        : "=r"(r[0]),"=r"(r[1]),"=r"(r[2]),"=r"(r[3]) : "r"(a));
}
__device__ __forceinline__ void ldm4t(uint32_t* r, uint32_t a){
    asm volatile("ldmatrix.sync.aligned.m8n8.x4.trans.shared.b16 {%0,%1,%2,%3}, [%4];"
        : "=r"(r[0]),"=r"(r[1]),"=r"(r[2]),"=r"(r[3]) : "r"(a));
}
__device__ __forceinline__ void mma16816(float* c, const uint32_t* a, uint32_t b0, uint32_t b1){
    asm volatile("mma.sync.aligned.m16n8k16.row.col.f32.f16.f16.f32 "
        "{%0,%1,%2,%3}, {%4,%5,%6,%7}, {%8,%9}, {%0,%1,%2,%3};"
        : "+f"(c[0]),"+f"(c[1]),"+f"(c[2]),"+f"(c[3])
        : "r"(a[0]),"r"(a[1]),"r"(a[2]),"r"(a[3]),"r"(b0),"r"(b1));
}
__device__ __forceinline__ float fexp2(float v){
    float r;
    asm("ex2.approx.ftz.f32 %0, %1;" : "=f"(r) : "f"(v));
    return r;
}
__device__ __forceinline__ __half2 split_hi2(float v0, float v1, __half& h0, __half& h1){
    h0 = __float2half_rn(v0); h1 = __float2half_rn(v1);
    return __halves2half2(h0, h1);
}
__device__ __forceinline__ __half2 split_lo2(float v0, float v1, __half h0, __half h1){
    return __halves2half2(__float2half_rn(v0 - __half2float(h0)),
                          __float2half_rn(v1 - __half2float(h1)));
}

// ============================================================
// Kernel 1: fused K/V projection. grid(128,2): y=0 -> K, y=1 -> V
// 4 warps x 32 rows; out[m,o] = sum_i x[m,i]*w[o,i] + b[o]
// ============================================================
#define PJ_XS 40

__global__ __launch_bounds__(128) void proj_kernel(
    const float* __restrict__ x,
    const float* __restrict__ w_k, const float* __restrict__ b_k,
    const float* __restrict__ w_v, const float* __restrict__ b_v)
{
    __shared__ __half xs_h[128*PJ_XS], xs_l[128*PJ_XS];
    __shared__ __half ws_h[128*PJ_XS], ws_l[128*PJ_XS];

    const int tid = threadIdx.x, lane = tid & 31, wid = tid >> 5;
    const int m0 = blockIdx.x * 128;
    const float* w    = blockIdx.y ? w_v : w_k;
    const float* bias = blockIdx.y ? b_v : b_k;
    __half* outh = blockIdx.y ? g_Vhi : g_Khi;
    __half* outl = blockIdx.y ? g_Vlo : g_Klo;

    float acc[2][16][4];
    #pragma unroll
    for (int mb = 0; mb < 2; mb++)
        #pragma unroll
        for (int nt = 0; nt < 16; nt++)
            #pragma unroll
            for (int q = 0; q < 4; q++) acc[mb][nt][q] = 0.f;

    const int fr = lane & 15, fc = (lane >> 4) << 3;
    const uint32_t aH0 = sptr(xs_h) + (uint32_t)(((wid*32      + fr)*PJ_XS + fc)*2);
    const uint32_t aH1 = sptr(xs_h) + (uint32_t)(((wid*32 + 16 + fr)*PJ_XS + fc)*2);
    const uint32_t aL0 = sptr(xs_l) + (uint32_t)(((wid*32      + fr)*PJ_XS + fc)*2);
    const uint32_t aL1 = sptr(xs_l) + (uint32_t)(((wid*32 + 16 + fr)*PJ_XS + fc)*2);
    const uint32_t bH  = sptr(ws_h) + (uint32_t)((fr*PJ_XS + fc)*2);
    const uint32_t bL  = sptr(ws_l) + (uint32_t)((fr*PJ_XS + fc)*2);

    for (int k0 = 0; k0 < DX; k0 += 32){
        #pragma unroll
        for (int e = tid; e < 128*8; e += 128){
            int r = e >> 3, c4 = (e & 7) << 2;
            float4 v = *reinterpret_cast<const float4*>(x + (size_t)(m0 + r)*DX + k0 + c4);
            __half h0,h1,h2,h3;
            *reinterpret_cast<__half2*>(xs_h + r*PJ_XS + c4)     = split_hi2(v.x, v.y, h0, h1);
            *reinterpret_cast<__half2*>(xs_h + r*PJ_XS + c4 + 2) = split_hi2(v.z, v.w, h2, h3);
            *reinterpret_cast<__half2*>(xs_l + r*PJ_XS + c4)     = split_lo2(v.x, v.y, h0, h1);
            *reinterpret_cast<__half2*>(xs_l + r*PJ_XS + c4 + 2) = split_lo2(v.z, v.w, h2, h3);
            float4 wv = *reinterpret_cast<const float4*>(w + (size_t)r*DX + k0 + c4);
            *reinterpret_cast<__half2*>(ws_h + r*PJ_XS + c4)     = split_hi2(wv.x, wv.y, h0, h1);
            *reinterpret_cast<__half2*>(ws_h + r*PJ_XS + c4 + 2) = split_hi2(wv.z, wv.w, h2, h3);
            *reinterpret_cast<__half2*>(ws_l + r*PJ_XS + c4)     = split_lo2(wv.x, wv.y, h0, h1);
            *reinterpret_cast<__half2*>(ws_l + r*PJ_XS + c4 + 2) = split_lo2(wv.z, wv.w, h2, h3);
        }
        __syncthreads();

        #pragma unroll
        for (int kk = 0; kk < 2; kk++){
            uint32_t ah[2][4], al[2][4];
            ldm4(ah[0], aH0 + kk*32);
            ldm4(ah[1], aH1 + kk*32);
            ldm4(al[0], aL0 + kk*32);
            ldm4(al[1], aL1 + kk*32);
            #pragma unroll
            for (int np = 0; np < 8; np++){
                uint32_t bh[4], bl[4];
                ldm4(bh, bH + np*16*PJ_XS*2 + kk*32);
                ldm4(bl, bL + np*16*PJ_XS*2 + kk*32);
                #pragma unroll
                for (int mb = 0; mb < 2; mb++)
                    #pragma unroll
                    for (int nn = 0; nn < 2; nn++){
                        float* c = acc[mb][np*2+nn];
                        mma16816(c, ah[mb], bh[nn], bh[nn+2]);
                        mma16816(c, ah[mb], bl[nn], bl[nn+2]);
                        mma16816(c, al[mb], bh[nn], bh[nn+2]);
                    }
            }
        }
        __syncthreads();
    }

    const int r0 = lane >> 2, q2 = (lane & 3) << 1;
    #pragma unroll
    for (int mb = 0; mb < 2; mb++){
        size_t grow0 = (size_t)(m0 + wid*32 + mb*16 + r0);
        #pragma unroll
        for (int nt = 0; nt < 16; nt++){
            int col = nt*8 + q2;
            float bb0 = bias[col], bb1 = bias[col+1];
            float v0 = acc[mb][nt][0] + bb0, v1 = acc[mb][nt][1] + bb1;
            float v2 = acc[mb][nt][2] + bb0, v3 = acc[mb][nt][3] + bb1;
            __half h0,h1,h2,h3;
            *reinterpret_cast<__half2*>(outh + grow0*DK + col)     = split_hi2(v0, v1, h0, h1);
            *reinterpret_cast<__half2*>(outl + grow0*DK + col)     = split_lo2(v0, v1, h0, h1);
            *reinterpret_cast<__half2*>(outh + (grow0+8)*DK + col) = split_hi2(v2, v3, h2, h3);
            *reinterpret_cast<__half2*>(outl + (grow0+8)*DK + col) = split_lo2(v2, v3, h2, h3);
        }
    }
}

// ============================================================
// Kernel 2: flash attention. queries = proj-K rows, keys = values = proj-V.
// grid(16,8): x = 128-row query tile, y = batch. 8 warps x 16 rows.
// ============================================================
#define AT_S 136
#define T_QH 0
#define T_QL (128*AT_S)
#define T_VH (2*128*AT_S)
#define T_VL (3*128*AT_S)
#define T_PH (4*128*AT_S)
#define T_PL (5*128*AT_S)
#define ATTN_SMEM (6*128*AT_S*2)

__global__ __launch_bounds__(256, 1) void attn_kernel(float* __restrict__ out)
{
    extern __shared__ __half sm[];
    const int tid = threadIdx.x, lane = tid & 31, wid = tid >> 5;
    const int b = blockIdx.y, mt = blockIdx.x;
    const size_t qbase = ((size_t)b*SEQ + (size_t)mt*128) * DK;

    for (int e = tid; e < 128*16; e += 256){
        int r = e >> 4, c8 = (e & 15) << 3;
        *reinterpret_cast<uint4*>(sm + T_QH + r*AT_S + c8) =
            *reinterpret_cast<const uint4*>(g_Khi + qbase + (size_t)r*DK + c8);
        *reinterpret_cast<uint4*>(sm + T_QL + r*AT_S + c8) =
            *reinterpret_cast<const uint4*>(g_Klo + qbase + (size_t)r*DK + c8);
    }

    float o[16][4];
    #pragma unroll
    for (int nt = 0; nt < 16; nt++)
        #pragma unroll
        for (int q = 0; q < 4; q++) o[nt][q] = 0.f;

    float mrun0 = -INFINITY, mrun1 = -INFINITY, lsum0 = 0.f, lsum1 = 0.f;

    const int m0w = wid * 16;
    const int fr = lane & 15, fc = (lane >> 4) << 3;
    const uint32_t smb = sptr(sm);
    const uint32_t aQ  = smb + (uint32_t)((T_QH + (m0w+fr)*AT_S + fc)*2);
    const uint32_t aQl = smb + (uint32_t)((T_QL + (m0w+fr)*AT_S + fc)*2);
    const uint32_t bS  = smb + (uint32_t)((T_VH + fr*AT_S + fc)*2);
    const uint32_t bSl = smb + (uint32_t)((T_VL + fr*AT_S + fc)*2);
    const uint32_t aP  = smb + (uint32_t)((T_PH + (m0w+fr)*AT_S + fc)*2);
    const uint32_t aPl = smb + (uint32_t)((T_PL + (m0w+fr)*AT_S + fc)*2);
    const int tr = (lane & 7) + ((lane >> 4) << 3);
    const int tc = ((lane >> 3) & 1) << 3;
    const uint32_t bO  = smb + (uint32_t)((T_VH + tr*AT_S + tc)*2);
    const uint32_t bOl = smb + (uint32_t)((T_VL + tr*AT_S + tc)*2);

    const int r0 = lane >> 2, q2 = (lane & 3) << 1;
    __half* pSt_h = sm + T_PH + (m0w + r0)*AT_S + q2;
    __half* pSt_l = sm + T_PL + (m0w + r0)*AT_S + q2;
    const float cS = 0.08838834764831845f * 1.4426950408889634f; // 1/sqrt(128)*log2(e)

    for (int j = 0; j < 16; j++){
        __syncthreads();
        const size_t vbase = ((size_t)b*SEQ + (size_t)j*128) * DK;
        for (int e = tid; e < 128*16; e += 256){
            int r = e >> 4, c8 = (e & 15) << 3;
            *reinterpret_cast<uint4*>(sm + T_VH + r*AT_S + c8) =
                *reinterpret_cast<const uint4*>(g_Vhi + vbase + (size_t)r*DK + c8);
            *reinterpret_cast<uint4*>(sm + T_VL + r*AT_S + c8) =
                *reinterpret_cast<const uint4*>(g_Vlo + vbase + (size_t)r*DK + c8);
        }
        __syncthreads();

        // S = Q @ V^T
        float s[16][4];
        #pragma unroll
        for (int nt = 0; nt < 16; nt++)
            #pragma unroll
            for (int q = 0; q < 4; q++) s[nt][q] = 0.f;

        #pragma unroll
        for (int kk = 0; kk < 8; kk++){
            uint32_t ah[4], al[4];
            ldm4(ah, aQ  + kk*32);
            ldm4(al, aQl + kk*32);
            #pragma unroll
            for (int np = 0; np < 8; np++){
                uint32_t bh[4], bl[4];
                ldm4(bh, bS  + np*16*AT_S*2 + kk*32);
                ldm4(bl, bSl + np*16*AT_S*2 + kk*32);
                #pragma unroll
                for (int nn = 0; nn < 2; nn++){
                    float* c = s[np*2+nn];
                    mma16816(c, ah, bh[nn], bh[nn+2]);
                    mma16816(c, ah, bl[nn], bl[nn+2]);
                    mma16816(c, al, bh[nn], bh[nn+2]);
                }
            }
        }

        // online softmax (exp2 domain)
        float mx0 = -INFINITY, mx1 = -INFINITY;
        #pragma unroll
        for (int nt = 0; nt < 16; nt++){
            mx0 = fmaxf(mx0, fmaxf(s[nt][0], s[nt][1]));
            mx1 = fmaxf(mx1, fmaxf(s[nt][2], s[nt][3]));
        }
        mx0 = fmaxf(mx0, __shfl_xor_sync(0xffffffffu, mx0, 1));
        mx0 = fmaxf(mx0, __shfl_xor_sync(0xffffffffu, mx0, 2));
        mx1 = fmaxf(mx1, __shfl_xor_sync(0xffffffffu, mx1, 1));
        mx1 = fmaxf(mx1, __shfl_xor_sync(0xffffffffu, mx1, 2));
        mx0 *= cS; mx1 *= cS;
        float mn0 = fmaxf(mrun0, mx0), mn1 = fmaxf(mrun1, mx1);
        float al0 = fexp2(mrun0 - mn0), al1 = fexp2(mrun1 - mn1);
        mrun0 = mn0; mrun1 = mn1;

        float rs0 = 0.f, rs1 = 0.f;
        #pragma unroll
        for (int nt = 0; nt < 16; nt++){
            float p00 = fexp2(fmaf(s[nt][0], cS, -mn0));
            float p01 = fexp2(fmaf(s[nt][1], cS, -mn0));
            float p10 = fexp2(fmaf(s[nt][2], cS, -mn1));
            float p11 = fexp2(fmaf(s[nt][3], cS, -mn1));
            rs0 += p00 + p01; rs1 += p10 + p11;
            __half h00,h01,h10,h11;
            *reinterpret_cast<__half2*>(pSt_h + nt*8)          = split_hi2(p00, p01, h00, h01);
            *reinterpret_cast<__half2*>(pSt_h + 8*AT_S + nt*8) = split_hi2(p10, p11, h10, h11);
            *reinterpret_cast<__half2*>(pSt_l + nt*8)          = split_lo2(p00, p01, h00, h01);
            *reinterpret_cast<__half2*>(pSt_l + 8*AT_S + nt*8) = split_lo2(p10, p11, h10, h11);
        }
        rs0 += __shfl_xor_sync(0xffffffffu, rs0, 1);
        rs0 += __shfl_xor_sync(0xffffffffu, rs0, 2);
        rs1 += __shfl_xor_sync(0xffffffffu, rs1, 1);
        rs1 += __shfl_xor_sync(0xffffffffu, rs1, 2);
        lsum0 = lsum0*al0 + rs0;
        lsum1 = lsum1*al1 + rs1;

        #pragma unroll
        for (int nt = 0; nt < 16; nt++){
            o[nt][0] *= al0; o[nt][1] *= al0;
            o[nt][2] *= al1; o[nt][3] *= al1;
        }
        __syncwarp();

        // O += P @ V   (V loaded transposed: k = key row, n = headdim)
        #pragma unroll
        for (int kk = 0; kk < 8; kk++){
            uint32_t ah[4], al_[4];
            ldm4(ah,  aP  + kk*32);
            ldm4(al_, aPl + kk*32);
            #pragma unroll
            for (int np = 0; np < 8; np++){
                uint32_t bh[4], bl[4];
                ldm4t(bh, bO  + kk*16*AT_S*2 + np*16*2);
                ldm4t(bl, bOl + kk*16*AT_S*2 + np*16*2);
                #pragma unroll
                for (int nn = 0; nn < 2; nn++){
                    float* c = o[np*2+nn];
                    mma16816(c, ah,  bh[nn], bh[nn+2]);
                    mma16816(c, ah,  bl[nn], bl[nn+2]);
                    mma16816(c, al_, bh[nn], bh[nn+2]);
                }
            }
        }
        __syncwarp();
    }

    // epilogue: normalize and store
    const float inv0 = 1.f / lsum0, inv1 = 1.f / lsum1;
    const size_t row0 = (size_t)b*SEQ + (size_t)mt*128 + m0w + r0;
    #pragma unroll
    for (int nt = 0; nt < 16; nt++){
        int col = nt*8 + q2;
        float2 v0 = make_float2(o[nt][0]*inv0, o[nt][1]*inv0);
        float2 v1 = make_float2(o[nt][2]*inv1, o[nt][3]*inv1);
        *reinterpret_cast<float2*>(out + row0*DK + col)     = v0;
        *reinterpret_cast<float2*>(out + (row0+8)*DK + col) = v1;
    }
}

extern "C" void kernel_launch(void* const* d_in, const int* in_sizes, int n_in,
                              void* d_out, int out_size)
{
    const float* x  = (const float*)d_in[0];
    const float* wk = (const float*)d_in[3];
    const float* bk = (const float*)d_in[4];
    const float* wv = (const float*)d_in[5];
    const float* bv = (const float*)d_in[6];
    (void)in_sizes; (void)n_in; (void)out_size;

    cudaFuncSetAttribute(attn_kernel, cudaFuncAttributeMaxDynamicSharedMemorySize, ATTN_SMEM);

    proj_kernel<<<dim3(128,2), 128>>>(x, wk, bk, wv, bv);
    attn_kernel<<<dim3(16,8), 256, ATTN_SMEM>>>((float*)d_out);
}

// round 4
// speedup vs baseline: 1.5428x; 1.5428x over previous
#include <cuda_runtime.h>
#include <cuda_fp16.h>
#include <cstdint>
#include <cmath>

#define DX 1024
#define DK 128
#define SEQ 2048
#define MTOT (8*SEQ)

__device__ __half g_Kh[MTOT*DK];
__device__ __half g_Vh[MTOT*DK];

__device__ __forceinline__ uint32_t sptr(const void* p){
    return (uint32_t)__cvta_generic_to_shared(p);
}
__device__ __forceinline__ void ldm4(uint32_t* r, uint32_t a){
    asm volatile("ldmatrix.sync.aligned.m8n8.x4.shared.b16 {%0,%1,%2,%3}, [%4];"
        : "=r"(r[0]),"=r"(r[1]),"=r"(r[2]),"=r"(r[3]) : "r"(a));
}
__device__ __forceinline__ void ldm4t(uint32_t* r, uint32_t a){
    asm volatile("ldmatrix.sync.aligned.m8n8.x4.trans.shared.b16 {%0,%1,%2,%3}, [%4];"
        : "=r"(r[0]),"=r"(r[1]),"=r"(r[2]),"=r"(r[3]) : "r"(a));
}
__device__ __forceinline__ void mma16816(float* c, const uint32_t* a, uint32_t b0, uint32_t b1){
    asm volatile("mma.sync.aligned.m16n8k16.row.col.f32.f16.f16.f32 "
        "{%0,%1,%2,%3}, {%4,%5,%6,%7}, {%8,%9}, {%0,%1,%2,%3};"
        : "+f"(c[0]),"+f"(c[1]),"+f"(c[2]),"+f"(c[3])
        : "r"(a[0]),"r"(a[1]),"r"(a[2]),"r"(a[3]),"r"(b0),"r"(b1));
}
__device__ __forceinline__ float fexp2(float v){
    float r;
    asm("ex2.approx.ftz.f32 %0, %1;" : "=f"(r) : "f"(v));
    return r;
}

// ============================================================
// Kernel 1: fused K & V projection, plain fp16 MMA.
// grid(128), 256 threads. warps 0-3 -> K, warps 4-7 -> V.
// out[m,o] = sum_i x[m,i]*w[o,i] + b[o], stored as fp16.
// ============================================================
#define PJ_XS 40

__global__ __launch_bounds__(256) void proj_kernel(
    const float* __restrict__ x,
    const float* __restrict__ w_k, const float* __restrict__ b_k,
    const float* __restrict__ w_v, const float* __restrict__ b_v)
{
    __shared__ __half xs[128*PJ_XS];
    __shared__ __half wks[128*PJ_XS];
    __shared__ __half wvs[128*PJ_XS];

    const int tid = threadIdx.x, lane = tid & 31, wid = tid >> 5;
    const int m0 = blockIdx.x * 128;
    const bool isV = (wid >= 4);
    const int wsub = wid & 3;                 // warp index within its group
    const float* bias = isV ? b_v : b_k;
    __half* outp = isV ? g_Vh : g_Kh;
    const __half* ws = isV ? wvs : wks;

    float acc[2][16][4];
    #pragma unroll
    for (int mb = 0; mb < 2; mb++)
        #pragma unroll
        for (int nt = 0; nt < 16; nt++)
            #pragma unroll
            for (int q = 0; q < 4; q++) acc[mb][nt][q] = 0.f;

    const int fr = lane & 15, fc = (lane >> 4) << 3;
    const uint32_t aH0 = sptr(xs) + (uint32_t)(((wsub*32      + fr)*PJ_XS + fc)*2);
    const uint32_t aH1 = sptr(xs) + (uint32_t)(((wsub*32 + 16 + fr)*PJ_XS + fc)*2);
    const uint32_t bH  = sptr(ws) + (uint32_t)((fr*PJ_XS + fc)*2);

    for (int k0 = 0; k0 < DX; k0 += 32){
        // 128 rows x 32 cols each of x, w_k, w_v  (f32 -> fp16 in smem)
        #pragma unroll
        for (int e = tid; e < 128*8; e += 256){
            int r = e >> 3, c4 = (e & 7) << 2;
            float4 v = *reinterpret_cast<const float4*>(x + (size_t)(m0 + r)*DX + k0 + c4);
            *reinterpret_cast<__half2*>(xs + r*PJ_XS + c4)     = __floats2half2_rn(v.x, v.y);
            *reinterpret_cast<__half2*>(xs + r*PJ_XS + c4 + 2) = __floats2half2_rn(v.z, v.w);
            float4 a = *reinterpret_cast<const float4*>(w_k + (size_t)r*DX + k0 + c4);
            *reinterpret_cast<__half2*>(wks + r*PJ_XS + c4)     = __floats2half2_rn(a.x, a.y);
            *reinterpret_cast<__half2*>(wks + r*PJ_XS + c4 + 2) = __floats2half2_rn(a.z, a.w);
            float4 bvv = *reinterpret_cast<const float4*>(w_v + (size_t)r*DX + k0 + c4);
            *reinterpret_cast<__half2*>(wvs + r*PJ_XS + c4)     = __floats2half2_rn(bvv.x, bvv.y);
            *reinterpret_cast<__half2*>(wvs + r*PJ_XS + c4 + 2) = __floats2half2_rn(bvv.z, bvv.w);
        }
        __syncthreads();

        #pragma unroll
        for (int kk = 0; kk < 2; kk++){
            uint32_t ah[2][4];
            ldm4(ah[0], aH0 + kk*32);
            ldm4(ah[1], aH1 + kk*32);
            #pragma unroll
            for (int np = 0; np < 8; np++){
                uint32_t bh[4];
                ldm4(bh, bH + np*16*PJ_XS*2 + kk*32);
                #pragma unroll
                for (int mb = 0; mb < 2; mb++)
                    #pragma unroll
                    for (int nn = 0; nn < 2; nn++)
                        mma16816(acc[mb][np*2+nn], ah[mb], bh[nn], bh[nn+2]);
            }
        }
        __syncthreads();
    }

    const int r0 = lane >> 2, q2 = (lane & 3) << 1;
    #pragma unroll
    for (int mb = 0; mb < 2; mb++){
        size_t grow0 = (size_t)(m0 + wsub*32 + mb*16 + r0);
        #pragma unroll
        for (int nt = 0; nt < 16; nt++){
            int col = nt*8 + q2;
            float bb0 = bias[col], bb1 = bias[col+1];
            *reinterpret_cast<__half2*>(outp + grow0*DK + col) =
                __floats2half2_rn(acc[mb][nt][0] + bb0, acc[mb][nt][1] + bb1);
            *reinterpret_cast<__half2*>(outp + (grow0+8)*DK + col) =
                __floats2half2_rn(acc[mb][nt][2] + bb0, acc[mb][nt][3] + bb1);
        }
    }
}

// ============================================================
// Kernel 2: flash attention, plain fp16.
// queries = proj-K rows, keys = values = proj-V rows.
// grid(32,8): x = 64-row query tile, y = batch. 4 warps x 16 rows.
// j-loop: 32 tiles of 64 keys.
// ============================================================
#define AT_S 136
#define P_S  72

__global__ __launch_bounds__(128) void attn_kernel(float* __restrict__ out)
{
    __shared__ __half smQ[64*AT_S];
    __shared__ __half smV[64*AT_S];
    __shared__ __half smP[64*P_S];

    const int tid = threadIdx.x, lane = tid & 31, wid = tid >> 5;
    const int b = blockIdx.y, mt = blockIdx.x;
    const size_t qbase = ((size_t)b*SEQ + (size_t)mt*64) * DK;

    // load Q tile (64 x 128 fp16)
    for (int e = tid; e < 64*16; e += 128){
        int r = e >> 4, c8 = (e & 15) << 3;
        *reinterpret_cast<uint4*>(smQ + r*AT_S + c8) =
            *reinterpret_cast<const uint4*>(g_Kh + qbase + (size_t)r*DK + c8);
    }

    float o[16][4];
    #pragma unroll
    for (int nt = 0; nt < 16; nt++)
        #pragma unroll
        for (int q = 0; q < 4; q++) o[nt][q] = 0.f;

    float mrun0 = -INFINITY, mrun1 = -INFINITY, lsum0 = 0.f, lsum1 = 0.f;

    const int m0w = wid * 16;
    const int fr = lane & 15, fc = (lane >> 4) << 3;
    const uint32_t aQ = sptr(smQ) + (uint32_t)(((m0w+fr)*AT_S + fc)*2);
    const uint32_t bV = sptr(smV) + (uint32_t)((fr*AT_S + fc)*2);
    const uint32_t aP = sptr(smP) + (uint32_t)(((m0w+fr)*P_S + fc)*2);
    const int tr = (lane & 7) + ((lane >> 4) << 3);
    const int tc = ((lane >> 3) & 1) << 3;
    const uint32_t bO = sptr(smV) + (uint32_t)((tr*AT_S + tc)*2);

    const int r0 = lane >> 2, q2 = (lane & 3) << 1;
    __half* pSt = smP + (m0w + r0)*P_S + q2;
    const float cS = 0.08838834764831845f * 1.4426950408889634f; // 1/sqrt(128)*log2(e)

    for (int j = 0; j < 32; j++){
        __syncthreads();   // previous iteration done with smV
        const size_t vbase = ((size_t)b*SEQ + (size_t)j*64) * DK;
        for (int e = tid; e < 64*16; e += 128){
            int r = e >> 4, c8 = (e & 15) << 3;
            *reinterpret_cast<uint4*>(smV + r*AT_S + c8) =
                *reinterpret_cast<const uint4*>(g_Vh + vbase + (size_t)r*DK + c8);
        }
        __syncthreads();

        // S = Q @ V^T  (16 q-rows x 64 keys per warp)
        float s[8][4];
        #pragma unroll
        for (int nt = 0; nt < 8; nt++)
            #pragma unroll
            for (int q = 0; q < 4; q++) s[nt][q] = 0.f;

        #pragma unroll
        for (int kk = 0; kk < 8; kk++){
            uint32_t ah[4];
            ldm4(ah, aQ + kk*32);
            #pragma unroll
            for (int np = 0; np < 4; np++){
                uint32_t bh[4];
                ldm4(bh, bV + np*16*AT_S*2 + kk*32);
                #pragma unroll
                for (int nn = 0; nn < 2; nn++)
                    mma16816(s[np*2+nn], ah, bh[nn], bh[nn+2]);
            }
        }

        // online softmax (exp2 domain)
        float mx0 = -INFINITY, mx1 = -INFINITY;
        #pragma unroll
        for (int nt = 0; nt < 8; nt++){
            mx0 = fmaxf(mx0, fmaxf(s[nt][0], s[nt][1]));
            mx1 = fmaxf(mx1, fmaxf(s[nt][2], s[nt][3]));
        }
        mx0 = fmaxf(mx0, __shfl_xor_sync(0xffffffffu, mx0, 1));
        mx0 = fmaxf(mx0, __shfl_xor_sync(0xffffffffu, mx0, 2));
        mx1 = fmaxf(mx1, __shfl_xor_sync(0xffffffffu, mx1, 1));
        mx1 = fmaxf(mx1, __shfl_xor_sync(0xffffffffu, mx1, 2));
        mx0 *= cS; mx1 *= cS;
        float mn0 = fmaxf(mrun0, mx0), mn1 = fmaxf(mrun1, mx1);
        float al0 = fexp2(mrun0 - mn0), al1 = fexp2(mrun1 - mn1);
        mrun0 = mn0; mrun1 = mn1;

        float rs0 = 0.f, rs1 = 0.f;
        #pragma unroll
        for (int nt = 0; nt < 8; nt++){
            float p00 = fexp2(fmaf(s[nt][0], cS, -mn0));
            float p01 = fexp2(fmaf(s[nt][1], cS, -mn0));
            float p10 = fexp2(fmaf(s[nt][2], cS, -mn1));
            float p11 = fexp2(fmaf(s[nt][3], cS, -mn1));
            rs0 += p00 + p01; rs1 += p10 + p11;
            *reinterpret_cast<__half2*>(pSt + nt*8)         = __floats2half2_rn(p00, p01);
            *reinterpret_cast<__half2*>(pSt + 8*P_S + nt*8) = __floats2half2_rn(p10, p11);
        }
        rs0 += __shfl_xor_sync(0xffffffffu, rs0, 1);
        rs0 += __shfl_xor_sync(0xffffffffu, rs0, 2);
        rs1 += __shfl_xor_sync(0xffffffffu, rs1, 1);
        rs1 += __shfl_xor_sync(0xffffffffu, rs1, 2);
        lsum0 = lsum0*al0 + rs0;
        lsum1 = lsum1*al1 + rs1;

        #pragma unroll
        for (int nt = 0; nt < 16; nt++){
            o[nt][0] *= al0; o[nt][1] *= al0;
            o[nt][2] *= al1; o[nt][3] *= al1;
        }
        __syncwarp();   // P stores visible to whole warp before ldmatrix

        // O += P @ V   (V read transposed: k = key row, n = headdim col)
        #pragma unroll
        for (int kk = 0; kk < 4; kk++){
            uint32_t ah[4];
            ldm4(ah, aP + kk*32);
            #pragma unroll
            for (int np = 0; np < 8; np++){
                uint32_t bh[4];
                ldm4t(bh, bO + kk*16*AT_S*2 + np*16*2);
                #pragma unroll
                for (int nn = 0; nn < 2; nn++)
                    mma16816(o[np*2+nn], ah, bh[nn], bh[nn+2]);
            }
        }
        __syncwarp();
    }

    // epilogue: normalize, store
    const float inv0 = 1.f / lsum0, inv1 = 1.f / lsum1;
    const size_t row0 = (size_t)b*SEQ + (size_t)mt*64 + m0w + r0;
    #pragma unroll
    for (int nt = 0; nt < 16; nt++){
        int col = nt*8 + q2;
        *reinterpret_cast<float2*>(out + row0*DK + col) =
            make_float2(o[nt][0]*inv0, o[nt][1]*inv0);
        *reinterpret_cast<float2*>(out + (row0+8)*DK + col) =
            make_float2(o[nt][2]*inv1, o[nt][3]*inv1);
    }
}

extern "C" void kernel_launch(void* const* d_in, const int* in_sizes, int n_in,
                              void* d_out, int out_size)
{
    const float* x  = (const float*)d_in[0];
    const float* wk = (const float*)d_in[3];
    const float* bk = (const float*)d_in[4];
    const float* wv = (const float*)d_in[5];
    const float* bv = (const float*)d_in[6];
    (void)in_sizes; (void)n_in; (void)out_size;

    proj_kernel<<<128, 256>>>(x, wk, bk, wv, bv);
    attn_kernel<<<dim3(32,8), 128>>>((float*)d_out);
}

// round 5
// speedup vs baseline: 2.1506x; 1.3940x over previous
#include <cuda_runtime.h>
#include <cuda_fp16.h>
#include <cstdint>
#include <cmath>

#define DX 1024
#define DK 128
#define SEQ 2048
#define NB 8
#define MTOT (NB*SEQ)

__device__ __half g_Xh[MTOT*DX];
__device__ __half g_Wk[DK*DX];
__device__ __half g_Wv[DK*DX];
__device__ __half g_Kh[MTOT*DK];
__device__ __half g_Vh[MTOT*DK];
__device__ float  g_Op[2][MTOT*DK];
__device__ float  g_ml[2][2][MTOT];   // [z][0=m,1=l][row]

__device__ __forceinline__ uint32_t sptr(const void* p){
    return (uint32_t)__cvta_generic_to_shared(p);
}
__device__ __forceinline__ void cpa16(uint32_t dst, const void* src){
    asm volatile("cp.async.cg.shared.global [%0], [%1], 16;" :: "r"(dst), "l"(src));
}
__device__ __forceinline__ void cpa_commit(){
    asm volatile("cp.async.commit_group;" ::: "memory");
}
template<int N> __device__ __forceinline__ void cpa_wait(){
    asm volatile("cp.async.wait_group %0;" :: "n"(N) : "memory");
}
__device__ __forceinline__ void ldm4(uint32_t* r, uint32_t a){
    asm volatile("ldmatrix.sync.aligned.m8n8.x4.shared.b16 {%0,%1,%2,%3}, [%4];"
        : "=r"(r[0]),"=r"(r[1]),"=r"(r[2]),"=r"(r[3]) : "r"(a));
}
__device__ __forceinline__ void ldm4t(uint32_t* r, uint32_t a){
    asm volatile("ldmatrix.sync.aligned.m8n8.x4.trans.shared.b16 {%0,%1,%2,%3}, [%4];"
        : "=r"(r[0]),"=r"(r[1]),"=r"(r[2]),"=r"(r[3]) : "r"(a));
}
__device__ __forceinline__ void mma16816(float* c, const uint32_t* a, uint32_t b0, uint32_t b1){
    asm volatile("mma.sync.aligned.m16n8k16.row.col.f32.f16.f16.f32 "
        "{%0,%1,%2,%3}, {%4,%5,%6,%7}, {%8,%9}, {%0,%1,%2,%3};"
        : "+f"(c[0]),"+f"(c[1]),"+f"(c[2]),"+f"(c[3])
        : "r"(a[0]),"r"(a[1]),"r"(a[2]),"r"(a[3]),"r"(b0),"r"(b1));
}
__device__ __forceinline__ float fexp2(float v){
    float r;
    asm("ex2.approx.ftz.f32 %0, %1;" : "=f"(r) : "f"(v));
    return r;
}

// ============================================================
// Kernel 0: convert x, w_k, w_v to fp16
// ============================================================
__global__ __launch_bounds__(256) void cvt_kernel(
    const float* __restrict__ x, const float* __restrict__ wk,
    const float* __restrict__ wv)
{
    const int NX = MTOT*DX/4, NW = DK*DX/4;
    int i = blockIdx.x*256 + threadIdx.x;
    const float* src; __half* dst; int k;
    if (i < NX){ src = x; dst = g_Xh; k = i; }
    else if (i < NX+NW){ src = wk; dst = g_Wk; k = i-NX; }
    else if (i < NX+2*NW){ src = wv; dst = g_Wv; k = i-NX-NW; }
    else return;
    float4 v = reinterpret_cast<const float4*>(src)[k];
    __half2 h0 = __floats2half2_rn(v.x, v.y);
    __half2 h1 = __floats2half2_rn(v.z, v.w);
    uint2 u = make_uint2(*reinterpret_cast<uint32_t*>(&h0),
                         *reinterpret_cast<uint32_t*>(&h1));
    reinterpret_cast<uint2*>(dst)[k] = u;
}

// ============================================================
// Kernel 1: fused K & V projection, all-fp16, cp.async 2-stage.
// grid(128), 256 threads. warps 0-3 -> K, warps 4-7 -> V.
// ============================================================
#define PJS 72
#define PJ_STAGE (3*128*PJS)
#define PJ_SMEM (2*PJ_STAGE*2)

__global__ __launch_bounds__(256) void proj_kernel(
    const float* __restrict__ b_k, const float* __restrict__ b_v)
{
    extern __shared__ __half ps[];
    const int tid = threadIdx.x, lane = tid & 31, wid = tid >> 5;
    const int m0 = blockIdx.x * 128;
    const bool isV = (wid >= 4);
    const int wsub = wid & 3;

    // prefetch k-chunk ki (64 cols) of x, wk, wv into stage s
    auto prefetch = [&](int ki, int s){
        __half* base = ps + s*PJ_STAGE;
        #pragma unroll
        for (int t = 0; t < 12; t++){
            int e = tid + t*256;            // 0..3071
            int arr = e >> 10;              // 0:x 1:wk 2:wv (1024 chunks each)
            int rem = e & 1023;
            int r = rem >> 3, c = (rem & 7) * 8;
            const __half* src =
                (arr == 0 ? g_Xh + (size_t)(m0 + r)*DX :
                 arr == 1 ? g_Wk + (size_t)r*DX :
                            g_Wv + (size_t)r*DX) + ki*64 + c;
            cpa16(sptr(base + arr*128*PJS + r*PJS + c), src);
        }
        cpa_commit();
    };

    prefetch(0, 0);
    prefetch(1, 1);

    float acc[2][16][4];
    #pragma unroll
    for (int mb = 0; mb < 2; mb++)
        #pragma unroll
        for (int nt = 0; nt < 16; nt++)
            #pragma unroll
            for (int q = 0; q < 4; q++) acc[mb][nt][q] = 0.f;

    const int fr = lane & 15, fc = (lane >> 4) << 3;

    for (int ki = 0; ki < 16; ki++){
        int s = ki & 1;
        cpa_wait<1>();
        __syncthreads();
        __half* xs = ps + s*PJ_STAGE;
        __half* ws = xs + (isV ? 2 : 1)*128*PJS;
        uint32_t aH0 = sptr(xs) + (uint32_t)(((wsub*32 + fr)*PJS + fc)*2);
        uint32_t aH1 = aH0 + 16*PJS*2;
        uint32_t bH  = sptr(ws) + (uint32_t)((fr*PJS + fc)*2);

        #pragma unroll
        for (int kk = 0; kk < 4; kk++){
            uint32_t ah[2][4];
            ldm4(ah[0], aH0 + kk*32);
            ldm4(ah[1], aH1 + kk*32);
            #pragma unroll
            for (int np = 0; np < 8; np++){
                uint32_t bh[4];
                ldm4(bh, bH + np*16*PJS*2 + kk*32);
                #pragma unroll
                for (int mb = 0; mb < 2; mb++)
                    #pragma unroll
                    for (int nn = 0; nn < 2; nn++)
                        mma16816(acc[mb][np*2+nn], ah[mb], bh[nn], bh[nn+2]);
            }
        }
        __syncthreads();
        if (ki + 2 < 16) prefetch(ki + 2, s);
        else cpa_commit();              // keep group count in lockstep
    }

    const float* bias = isV ? b_v : b_k;
    __half* outp = isV ? g_Vh : g_Kh;
    const int r0 = lane >> 2, q2 = (lane & 3) << 1;
    #pragma unroll
    for (int mb = 0; mb < 2; mb++){
        size_t grow0 = (size_t)(m0 + wsub*32 + mb*16 + r0);
        #pragma unroll
        for (int nt = 0; nt < 16; nt++){
            int col = nt*8 + q2;
            float bb0 = bias[col], bb1 = bias[col+1];
            *reinterpret_cast<__half2*>(outp + grow0*DK + col) =
                __floats2half2_rn(acc[mb][nt][0] + bb0, acc[mb][nt][1] + bb1);
            *reinterpret_cast<__half2*>(outp + (grow0+8)*DK + col) =
                __floats2half2_rn(acc[mb][nt][2] + bb0, acc[mb][nt][3] + bb1);
        }
    }
}

// ============================================================
// Kernel 2: flash attention, split-K x2, cp.async ping-pong V.
// grid(32, 8, 2): x = 64-row q tile, y = batch, z = key half.
// 4 warps x 16 rows; 16 j-tiles of 64 keys per CTA.
// Writes unnormalized partial O + (m, l).
// ============================================================
#define AT_S 136
#define P_S  72
#define A_Q  0
#define A_V0 (64*AT_S)
#define A_V1 (2*64*AT_S)
#define A_P  (3*64*AT_S)
#define ATTN_SMEM ((3*64*AT_S + 64*P_S)*2)

__global__ __launch_bounds__(128) void attn_kernel()
{
    extern __shared__ __half sm[];
    const int tid = threadIdx.x, lane = tid & 31, wid = tid >> 5;
    const int b = blockIdx.y, mt = blockIdx.x, z = blockIdx.z;
    const size_t kvoff = (size_t)b*SEQ + (size_t)z*1024;

    auto prefetchV = [&](int j, int s){
        const __half* gv = g_Vh + (kvoff + (size_t)j*64)*DK;
        __half* base = sm + (s ? A_V1 : A_V0);
        #pragma unroll
        for (int t = 0; t < 8; t++){
            int e = tid + t*128;
            int r = e >> 4, c = (e & 15) * 8;
            cpa16(sptr(base + r*AT_S + c), gv + (size_t)r*DK + c);
        }
    };

    // prologue: Q + V(0) in group A; V(1) in group B
    {
        const __half* gq = g_Kh + ((size_t)b*SEQ + (size_t)mt*64)*DK;
        #pragma unroll
        for (int t = 0; t < 8; t++){
            int e = tid + t*128;
            int r = e >> 4, c = (e & 15) * 8;
            cpa16(sptr(sm + A_Q + r*AT_S + c), gq + (size_t)r*DK + c);
        }
        prefetchV(0, 0);
        cpa_commit();
        prefetchV(1, 1);
        cpa_commit();
    }

    float o[16][4];
    #pragma unroll
    for (int nt = 0; nt < 16; nt++)
        #pragma unroll
        for (int q = 0; q < 4; q++) o[nt][q] = 0.f;

    float mrun0 = -INFINITY, mrun1 = -INFINITY, lsum0 = 0.f, lsum1 = 0.f;

    const int m0w = wid * 16;
    const int fr = lane & 15, fc = (lane >> 4) << 3;
    const uint32_t smb = sptr(sm);
    const uint32_t aQ = smb + (uint32_t)((A_Q + (m0w+fr)*AT_S + fc)*2);
    const uint32_t aP = smb + (uint32_t)((A_P + (m0w+fr)*P_S + fc)*2);
    const int tr = (lane & 7) + ((lane >> 4) << 3);
    const int tc = ((lane >> 3) & 1) << 3;

    const int r0 = lane >> 2, q2 = (lane & 3) << 1;
    __half* pSt = sm + A_P + (m0w + r0)*P_S + q2;
    const float cS = 0.08838834764831845f * 1.4426950408889634f;

    for (int j = 0; j < 16; j++){
        const int s = j & 1;
        const uint32_t vb = (uint32_t)((s ? A_V1 : A_V0)*2);
        const uint32_t bV = smb + vb + (uint32_t)((fr*AT_S + fc)*2);
        const uint32_t bO = smb + vb + (uint32_t)((tr*AT_S + tc)*2);

        cpa_wait<1>();
        __syncthreads();

        // S = Q @ V^T
        float s_[8][4];
        #pragma unroll
        for (int nt = 0; nt < 8; nt++)
            #pragma unroll
            for (int q = 0; q < 4; q++) s_[nt][q] = 0.f;

        #pragma unroll
        for (int kk = 0; kk < 8; kk++){
            uint32_t ah[4];
            ldm4(ah, aQ + kk*32);
            #pragma unroll
            for (int np = 0; np < 4; np++){
                uint32_t bh[4];
                ldm4(bh, bV + np*16*AT_S*2 + kk*32);
                #pragma unroll
                for (int nn = 0; nn < 2; nn++)
                    mma16816(s_[np*2+nn], ah, bh[nn], bh[nn+2]);
            }
        }

        // online softmax (exp2 domain)
        float mx0 = -INFINITY, mx1 = -INFINITY;
        #pragma unroll
        for (int nt = 0; nt < 8; nt++){
            mx0 = fmaxf(mx0, fmaxf(s_[nt][0], s_[nt][1]));
            mx1 = fmaxf(mx1, fmaxf(s_[nt][2], s_[nt][3]));
        }
        mx0 = fmaxf(mx0, __shfl_xor_sync(0xffffffffu, mx0, 1));
        mx0 = fmaxf(mx0, __shfl_xor_sync(0xffffffffu, mx0, 2));
        mx1 = fmaxf(mx1, __shfl_xor_sync(0xffffffffu, mx1, 1));
        mx1 = fmaxf(mx1, __shfl_xor_sync(0xffffffffu, mx1, 2));
        mx0 *= cS; mx1 *= cS;
        float mn0 = fmaxf(mrun0, mx0), mn1 = fmaxf(mrun1, mx1);
        float al0 = fexp2(mrun0 - mn0), al1 = fexp2(mrun1 - mn1);
        mrun0 = mn0; mrun1 = mn1;

        float rs0 = 0.f, rs1 = 0.f;
        #pragma unroll
        for (int nt = 0; nt < 8; nt++){
            float p00 = fexp2(fmaf(s_[nt][0], cS, -mn0));
            float p01 = fexp2(fmaf(s_[nt][1], cS, -mn0));
            float p10 = fexp2(fmaf(s_[nt][2], cS, -mn1));
            float p11 = fexp2(fmaf(s_[nt][3], cS, -mn1));
            rs0 += p00 + p01; rs1 += p10 + p11;
            *reinterpret_cast<__half2*>(pSt + nt*8)         = __floats2half2_rn(p00, p01);
            *reinterpret_cast<__half2*>(pSt + 8*P_S + nt*8) = __floats2half2_rn(p10, p11);
        }
        rs0 += __shfl_xor_sync(0xffffffffu, rs0, 1);
        rs0 += __shfl_xor_sync(0xffffffffu, rs0, 2);
        rs1 += __shfl_xor_sync(0xffffffffu, rs1, 1);
        rs1 += __shfl_xor_sync(0xffffffffu, rs1, 2);
        lsum0 = lsum0*al0 + rs0;
        lsum1 = lsum1*al1 + rs1;

        #pragma unroll
        for (int nt = 0; nt < 16; nt++){
            o[nt][0] *= al0; o[nt][1] *= al0;
            o[nt][2] *= al1; o[nt][3] *= al1;
        }
        __syncwarp();

        // O += P @ V
        #pragma unroll
        for (int kk = 0; kk < 4; kk++){
            uint32_t ah[4];
            ldm4(ah, aP + kk*32);
            #pragma unroll
            for (int np = 0; np < 8; np++){
                uint32_t bh[4];
                ldm4t(bh, bO + kk*16*AT_S*2 + np*16*2);
                #pragma unroll
                for (int nn = 0; nn < 2; nn++)
                    mma16816(o[np*2+nn], ah, bh[nn], bh[nn+2]);
            }
        }
        __syncthreads();              // all warps done reading smV[s]
        if (j + 2 < 16) prefetchV(j + 2, s);
        cpa_commit();                 // always commit (group lockstep)
    }

    // epilogue: store unnormalized partial O + (m, l)
    float* Op = g_Op[z];
    const size_t row0 = (size_t)b*SEQ + (size_t)mt*64 + m0w + r0;
    #pragma unroll
    for (int nt = 0; nt < 16; nt++){
        int col = nt*8 + q2;
        *reinterpret_cast<float2*>(Op + row0*DK + col) =
            make_float2(o[nt][0], o[nt][1]);
        *reinterpret_cast<float2*>(Op + (row0+8)*DK + col) =
            make_float2(o[nt][2], o[nt][3]);
    }
    if ((lane & 3) == 0){
        g_ml[z][0][row0]   = mrun0;  g_ml[z][1][row0]   = lsum0;
        g_ml[z][0][row0+8] = mrun1;  g_ml[z][1][row0+8] = lsum1;
    }
}

// ============================================================
// Kernel 3: combine the two split-K partials.
// grid(2048), 256 threads: 8 rows/block, 32 threads/row (float4).
// ============================================================
__global__ __launch_bounds__(256) void combine_kernel(float* __restrict__ out)
{
    const int row = blockIdx.x*8 + (threadIdx.x >> 5);
    const int c4 = (threadIdx.x & 31) * 4;
    float m0 = g_ml[0][0][row], l0 = g_ml[0][1][row];
    float m1 = g_ml[1][0][row], l1 = g_ml[1][1][row];
    float m = fmaxf(m0, m1);
    float a0 = fexp2(m0 - m), a1 = fexp2(m1 - m);
    float inv = 1.f / (l0*a0 + l1*a1);
    float4 o0 = *reinterpret_cast<const float4*>(g_Op[0] + (size_t)row*DK + c4);
    float4 o1 = *reinterpret_cast<const float4*>(g_Op[1] + (size_t)row*DK + c4);
    float4 r;
    r.x = (o0.x*a0 + o1.x*a1)*inv;
    r.y = (o0.y*a0 + o1.y*a1)*inv;
    r.z = (o0.z*a0 + o1.z*a1)*inv;
    r.w = (o0.w*a0 + o1.w*a1)*inv;
    *reinterpret_cast<float4*>(out + (size_t)row*DK + c4) = r;
}

extern "C" void kernel_launch(void* const* d_in, const int* in_sizes, int n_in,
                              void* d_out, int out_size)
{
    const float* x  = (const float*)d_in[0];
    const float* wk = (const float*)d_in[3];
    const float* bk = (const float*)d_in[4];
    const float* wv = (const float*)d_in[5];
    const float* bv = (const float*)d_in[6];
    (void)in_sizes; (void)n_in; (void)out_size;

    cudaFuncSetAttribute(proj_kernel, cudaFuncAttributeMaxDynamicSharedMemorySize, PJ_SMEM);
    cudaFuncSetAttribute(attn_kernel, cudaFuncAttributeMaxDynamicSharedMemorySize, ATTN_SMEM);

    const int NX = MTOT*DX/4, NW = DK*DX/4;
    cvt_kernel<<<(NX + 2*NW + 255)/256, 256>>>(x, wk, wv);
    proj_kernel<<<128, 256, PJ_SMEM>>>(bk, bv);
    attn_kernel<<<dim3(32,8,2), 128, ATTN_SMEM>>>();
    combine_kernel<<<2048, 256>>>((float*)d_out);
}

// round 6
// speedup vs baseline: 2.2101x; 1.0276x over previous
#include <cuda_runtime.h>
#include <cuda_fp16.h>
#include <cstdint>
#include <cmath>

#define DX 1024
#define DK 128
#define SEQ 2048
#define NB 8
#define MTOT (NB*SEQ)

__device__ __half g_Xh[MTOT*DX];
__device__ __half g_Wk[DK*DX];
__device__ __half g_Wv[DK*DX];
__device__ __half g_Kh[MTOT*DK];
__device__ __half g_Vh[MTOT*DK];
__device__ __half g_Oph[2][MTOT*DK];
__device__ float  g_ml[2][2][MTOT];   // [z][0=m,1=l][row]

__device__ __forceinline__ uint32_t sptr(const void* p){
    return (uint32_t)__cvta_generic_to_shared(p);
}
__device__ __forceinline__ void cpa16(uint32_t dst, const void* src){
    asm volatile("cp.async.cg.shared.global [%0], [%1], 16;" :: "r"(dst), "l"(src));
}
__device__ __forceinline__ void cpa_commit(){
    asm volatile("cp.async.commit_group;" ::: "memory");
}
template<int N> __device__ __forceinline__ void cpa_wait(){
    asm volatile("cp.async.wait_group %0;" :: "n"(N) : "memory");
}
__device__ __forceinline__ void ldm4(uint32_t* r, uint32_t a){
    asm volatile("ldmatrix.sync.aligned.m8n8.x4.shared.b16 {%0,%1,%2,%3}, [%4];"
        : "=r"(r[0]),"=r"(r[1]),"=r"(r[2]),"=r"(r[3]) : "r"(a));
}
__device__ __forceinline__ void ldm4t(uint32_t* r, uint32_t a){
    asm volatile("ldmatrix.sync.aligned.m8n8.x4.trans.shared.b16 {%0,%1,%2,%3}, [%4];"
        : "=r"(r[0]),"=r"(r[1]),"=r"(r[2]),"=r"(r[3]) : "r"(a));
}
__device__ __forceinline__ void mma16816(float* c, const uint32_t* a, uint32_t b0, uint32_t b1){
    asm volatile("mma.sync.aligned.m16n8k16.row.col.f32.f16.f16.f32 "
        "{%0,%1,%2,%3}, {%4,%5,%6,%7}, {%8,%9}, {%0,%1,%2,%3};"
        : "+f"(c[0]),"+f"(c[1]),"+f"(c[2]),"+f"(c[3])
        : "r"(a[0]),"r"(a[1]),"r"(a[2]),"r"(a[3]),"r"(b0),"r"(b1));
}
__device__ __forceinline__ float fexp2(float v){
    float r;
    asm("ex2.approx.ftz.f32 %0, %1;" : "=f"(r) : "f"(v));
    return r;
}
__device__ __forceinline__ uint32_t packh2(float a, float b){
    __half2 h = __floats2half2_rn(a, b);
    return *reinterpret_cast<uint32_t*>(&h);
}

// ============================================================
// Kernel 0: convert x, w_k, w_v to fp16
// ============================================================
__global__ __launch_bounds__(256) void cvt_kernel(
    const float* __restrict__ x, const float* __restrict__ wk,
    const float* __restrict__ wv)
{
    const int NX = MTOT*DX/4, NW = DK*DX/4;
    int i = blockIdx.x*256 + threadIdx.x;
    const float* src; __half* dst; int k;
    if (i < NX){ src = x; dst = g_Xh; k = i; }
    else if (i < NX+NW){ src = wk; dst = g_Wk; k = i-NX; }
    else if (i < NX+2*NW){ src = wv; dst = g_Wv; k = i-NX-NW; }
    else return;
    float4 v = reinterpret_cast<const float4*>(src)[k];
    uint2 u = make_uint2(packh2(v.x, v.y), packh2(v.z, v.w));
    reinterpret_cast<uint2*>(dst)[k] = u;
}

// ============================================================
// Kernel 1: fused K & V projection, all-fp16, cp.async 2-stage.
// grid(128), 256 threads. warps 0-3 -> K, warps 4-7 -> V.
// ============================================================
#define PJS 72
#define PJ_STAGE (3*128*PJS)
#define PJ_SMEM (2*PJ_STAGE*2)

__global__ __launch_bounds__(256) void proj_kernel(
    const float* __restrict__ b_k, const float* __restrict__ b_v)
{
    extern __shared__ __half ps[];
    const int tid = threadIdx.x, lane = tid & 31, wid = tid >> 5;
    const int m0 = blockIdx.x * 128;
    const bool isV = (wid >= 4);
    const int wsub = wid & 3;

    auto prefetch = [&](int ki, int s){
        __half* base = ps + s*PJ_STAGE;
        #pragma unroll
        for (int t = 0; t < 12; t++){
            int e = tid + t*256;
            int arr = e >> 10;
            int rem = e & 1023;
            int r = rem >> 3, c = (rem & 7) * 8;
            const __half* src =
                (arr == 0 ? g_Xh + (size_t)(m0 + r)*DX :
                 arr == 1 ? g_Wk + (size_t)r*DX :
                            g_Wv + (size_t)r*DX) + ki*64 + c;
            cpa16(sptr(base + arr*128*PJS + r*PJS + c), src);
        }
        cpa_commit();
    };

    prefetch(0, 0);
    prefetch(1, 1);

    float acc[2][16][4];
    #pragma unroll
    for (int mb = 0; mb < 2; mb++)
        #pragma unroll
        for (int nt = 0; nt < 16; nt++)
            #pragma unroll
            for (int q = 0; q < 4; q++) acc[mb][nt][q] = 0.f;

    const int fr = lane & 15, fc = (lane >> 4) << 3;

    for (int ki = 0; ki < 16; ki++){
        int s = ki & 1;
        cpa_wait<1>();
        __syncthreads();
        __half* xs = ps + s*PJ_STAGE;
        __half* ws = xs + (isV ? 2 : 1)*128*PJS;
        uint32_t aH0 = sptr(xs) + (uint32_t)(((wsub*32 + fr)*PJS + fc)*2);
        uint32_t aH1 = aH0 + 16*PJS*2;
        uint32_t bH  = sptr(ws) + (uint32_t)((fr*PJS + fc)*2);

        #pragma unroll
        for (int kk = 0; kk < 4; kk++){
            uint32_t ah[2][4];
            ldm4(ah[0], aH0 + kk*32);
            ldm4(ah[1], aH1 + kk*32);
            #pragma unroll
            for (int np = 0; np < 8; np++){
                uint32_t bh[4];
                ldm4(bh, bH + np*16*PJS*2 + kk*32);
                #pragma unroll
                for (int mb = 0; mb < 2; mb++)
                    #pragma unroll
                    for (int nn = 0; nn < 2; nn++)
                        mma16816(acc[mb][np*2+nn], ah[mb], bh[nn], bh[nn+2]);
            }
        }
        __syncthreads();
        if (ki + 2 < 16) prefetch(ki + 2, s);
        else cpa_commit();
    }

    const float* bias = isV ? b_v : b_k;
    __half* outp = isV ? g_Vh : g_Kh;
    const int r0 = lane >> 2, q2 = (lane & 3) << 1;
    #pragma unroll
    for (int mb = 0; mb < 2; mb++){
        size_t grow0 = (size_t)(m0 + wsub*32 + mb*16 + r0);
        #pragma unroll
        for (int nt = 0; nt < 16; nt++){
            int col = nt*8 + q2;
            float bb0 = bias[col], bb1 = bias[col+1];
            *reinterpret_cast<__half2*>(outp + grow0*DK + col) =
                __floats2half2_rn(acc[mb][nt][0] + bb0, acc[mb][nt][1] + bb1);
            *reinterpret_cast<__half2*>(outp + (grow0+8)*DK + col) =
                __floats2half2_rn(acc[mb][nt][2] + bb0, acc[mb][nt][3] + bb1);
        }
    }
}

// ============================================================
// Kernel 2: flash attention, split-K x2, register-resident P.
// grid(32, 8, 2): x = 64-row q tile, y = batch, z = key half.
// 4 warps x 16 rows; 16 j-tiles of 64 keys per CTA.
// ============================================================
#define AT_S 136
#define A_Q  0
#define A_V0 (64*AT_S)
#define A_V1 (2*64*AT_S)
#define ATTN_SMEM (3*64*AT_S*2)

__global__ __launch_bounds__(128) void attn_kernel()
{
    extern __shared__ __half sm[];
    const int tid = threadIdx.x, lane = tid & 31, wid = tid >> 5;
    const int b = blockIdx.y, mt = blockIdx.x, z = blockIdx.z;
    const size_t kvoff = (size_t)b*SEQ + (size_t)z*1024;

    auto prefetchV = [&](int j, int s){
        const __half* gv = g_Vh + (kvoff + (size_t)j*64)*DK;
        __half* base = sm + (s ? A_V1 : A_V0);
        #pragma unroll
        for (int t = 0; t < 8; t++){
            int e = tid + t*128;
            int r = e >> 4, c = (e & 15) * 8;
            cpa16(sptr(base + r*AT_S + c), gv + (size_t)r*DK + c);
        }
    };

    {
        const __half* gq = g_Kh + ((size_t)b*SEQ + (size_t)mt*64)*DK;
        #pragma unroll
        for (int t = 0; t < 8; t++){
            int e = tid + t*128;
            int r = e >> 4, c = (e & 15) * 8;
            cpa16(sptr(sm + A_Q + r*AT_S + c), gq + (size_t)r*DK + c);
        }
        prefetchV(0, 0);
        cpa_commit();
        prefetchV(1, 1);
        cpa_commit();
    }

    float o[16][4];
    #pragma unroll
    for (int nt = 0; nt < 16; nt++)
        #pragma unroll
        for (int q = 0; q < 4; q++) o[nt][q] = 0.f;

    float mrun0 = -INFINITY, mrun1 = -INFINITY, lsum0 = 0.f, lsum1 = 0.f;

    const int m0w = wid * 16;
    const int fr = lane & 15, fc = (lane >> 4) << 3;
    const uint32_t smb = sptr(sm);
    const uint32_t aQ = smb + (uint32_t)((A_Q + (m0w+fr)*AT_S + fc)*2);
    const int tr = (lane & 7) + ((lane >> 4) << 3);
    const int tc = ((lane >> 3) & 1) << 3;

    const float cS = 0.08838834764831845f * 1.4426950408889634f;

    for (int j = 0; j < 16; j++){
        const int s = j & 1;
        const uint32_t vb = (uint32_t)((s ? A_V1 : A_V0)*2);
        const uint32_t bV = smb + vb + (uint32_t)((fr*AT_S + fc)*2);
        const uint32_t bO = smb + vb + (uint32_t)((tr*AT_S + tc)*2);

        cpa_wait<1>();
        __syncthreads();

        // S = Q @ V^T
        float s_[8][4];
        #pragma unroll
        for (int nt = 0; nt < 8; nt++)
            #pragma unroll
            for (int q = 0; q < 4; q++) s_[nt][q] = 0.f;

        #pragma unroll
        for (int kk = 0; kk < 8; kk++){
            uint32_t ah[4];
            ldm4(ah, aQ + kk*32);
            #pragma unroll
            for (int np = 0; np < 4; np++){
                uint32_t bh[4];
                ldm4(bh, bV + np*16*AT_S*2 + kk*32);
                #pragma unroll
                for (int nn = 0; nn < 2; nn++)
                    mma16816(s_[np*2+nn], ah, bh[nn], bh[nn+2]);
            }
        }

        // online softmax (exp2 domain), P packed straight into A-fragments
        float mx0 = -INFINITY, mx1 = -INFINITY;
        #pragma unroll
        for (int nt = 0; nt < 8; nt++){
            mx0 = fmaxf(mx0, fmaxf(s_[nt][0], s_[nt][1]));
            mx1 = fmaxf(mx1, fmaxf(s_[nt][2], s_[nt][3]));
        }
        mx0 = fmaxf(mx0, __shfl_xor_sync(0xffffffffu, mx0, 1));
        mx0 = fmaxf(mx0, __shfl_xor_sync(0xffffffffu, mx0, 2));
        mx1 = fmaxf(mx1, __shfl_xor_sync(0xffffffffu, mx1, 1));
        mx1 = fmaxf(mx1, __shfl_xor_sync(0xffffffffu, mx1, 2));
        mx0 *= cS; mx1 *= cS;
        float mn0 = fmaxf(mrun0, mx0), mn1 = fmaxf(mrun1, mx1);
        float al0 = fexp2(mrun0 - mn0), al1 = fexp2(mrun1 - mn1);
        mrun0 = mn0; mrun1 = mn1;

        uint32_t pf[16];
        float rs0 = 0.f, rs1 = 0.f;
        #pragma unroll
        for (int nt = 0; nt < 8; nt++){
            float p00 = fexp2(fmaf(s_[nt][0], cS, -mn0));
            float p01 = fexp2(fmaf(s_[nt][1], cS, -mn0));
            float p10 = fexp2(fmaf(s_[nt][2], cS, -mn1));
            float p11 = fexp2(fmaf(s_[nt][3], cS, -mn1));
            rs0 += p00 + p01; rs1 += p10 + p11;
            pf[nt*2]   = packh2(p00, p01);
            pf[nt*2+1] = packh2(p10, p11);
        }
        rs0 += __shfl_xor_sync(0xffffffffu, rs0, 1);
        rs0 += __shfl_xor_sync(0xffffffffu, rs0, 2);
        rs1 += __shfl_xor_sync(0xffffffffu, rs1, 1);
        rs1 += __shfl_xor_sync(0xffffffffu, rs1, 2);
        lsum0 = lsum0*al0 + rs0;
        lsum1 = lsum1*al1 + rs1;

        #pragma unroll
        for (int nt = 0; nt < 16; nt++){
            o[nt][0] *= al0; o[nt][1] *= al0;
            o[nt][2] *= al1; o[nt][3] *= al1;
        }

        // O += P @ V  (P in registers; V read transposed from smem)
        #pragma unroll
        for (int kk = 0; kk < 4; kk++){
            const uint32_t* a = pf + kk*4;
            #pragma unroll
            for (int np = 0; np < 8; np++){
                uint32_t bh[4];
                ldm4t(bh, bO + kk*16*AT_S*2 + np*16*2);
                #pragma unroll
                for (int nn = 0; nn < 2; nn++)
                    mma16816(o[np*2+nn], a, bh[nn], bh[nn+2]);
            }
        }
        __syncthreads();              // all warps done reading smV[s]
        if (j + 2 < 16) prefetchV(j + 2, s);
        cpa_commit();
    }

    // epilogue: store unnormalized partial O (fp16) + (m, l)
    __half* Op = g_Oph[z];
    const int r0 = lane >> 2, q2 = (lane & 3) << 1;
    const size_t row0 = (size_t)b*SEQ + (size_t)mt*64 + m0w + r0;
    #pragma unroll
    for (int nt = 0; nt < 16; nt++){
        int col = nt*8 + q2;
        *reinterpret_cast<__half2*>(Op + row0*DK + col) =
            __floats2half2_rn(o[nt][0], o[nt][1]);
        *reinterpret_cast<__half2*>(Op + (row0+8)*DK + col) =
            __floats2half2_rn(o[nt][2], o[nt][3]);
    }
    if ((lane & 3) == 0){
        g_ml[z][0][row0]   = mrun0;  g_ml[z][1][row0]   = lsum0;
        g_ml[z][0][row0+8] = mrun1;  g_ml[z][1][row0+8] = lsum1;
    }
}

// ============================================================
// Kernel 3: combine the two split-K partials.
// grid(2048), 256 threads: 8 rows/block, 32 threads/row.
// ============================================================
__global__ __launch_bounds__(256) void combine_kernel(float* __restrict__ out)
{
    const int row = blockIdx.x*8 + (threadIdx.x >> 5);
    const int c4 = (threadIdx.x & 31) * 4;
    float m0 = g_ml[0][0][row], l0 = g_ml[0][1][row];
    float m1 = g_ml[1][0][row], l1 = g_ml[1][1][row];
    float m = fmaxf(m0, m1);
    float a0 = fexp2(m0 - m), a1 = fexp2(m1 - m);
    float inv = 1.f / (l0*a0 + l1*a1);
    uint2 u0 = *reinterpret_cast<const uint2*>(g_Oph[0] + (size_t)row*DK + c4);
    uint2 u1 = *reinterpret_cast<const uint2*>(g_Oph[1] + (size_t)row*DK + c4);
    float2 p00 = __half22float2(*reinterpret_cast<__half2*>(&u0.x));
    float2 p01 = __half22float2(*reinterpret_cast<__half2*>(&u0.y));
    float2 p10 = __half22float2(*reinterpret_cast<__half2*>(&u1.x));
    float2 p11 = __half22float2(*reinterpret_cast<__half2*>(&u1.y));
    float4 r;
    r.x = (p00.x*a0 + p10.x*a1)*inv;
    r.y = (p00.y*a0 + p10.y*a1)*inv;
    r.z = (p01.x*a0 + p11.x*a1)*inv;
    r.w = (p01.y*a0 + p11.y*a1)*inv;
    *reinterpret_cast<float4*>(out + (size_t)row*DK + c4) = r;
}

extern "C" void kernel_launch(void* const* d_in, const int* in_sizes, int n_in,
                              void* d_out, int out_size)
{
    const float* x  = (const float*)d_in[0];
    const float* wk = (const float*)d_in[3];
    const float* bk = (const float*)d_in[4];
    const float* wv = (const float*)d_in[5];
    const float* bv = (const float*)d_in[6];
    (void)in_sizes; (void)n_in; (void)out_size;

    cudaFuncSetAttribute(proj_kernel, cudaFuncAttributeMaxDynamicSharedMemorySize, PJ_SMEM);
    cudaFuncSetAttribute(attn_kernel, cudaFuncAttributeMaxDynamicSharedMemorySize, ATTN_SMEM);

    const int NX = MTOT*DX/4, NW = DK*DX/4;
    cvt_kernel<<<(NX + 2*NW + 255)/256, 256>>>(x, wk, wv);
    proj_kernel<<<128, 256, PJ_SMEM>>>(bk, bv);
    attn_kernel<<<dim3(32,8,2), 128, ATTN_SMEM>>>();
    combine_kernel<<<2048, 256>>>((float*)d_out);
}